// round 14
// baseline (speedup 1.0000x reference)
#include <cuda_runtime.h>
#include <cstdint>

// Problem constants
#define B 32
#define L 6
#define R 8
#define H 64
#define NTRAJ 262144              // R^L
#define F4_PER_B 393216           // NTRAJ * L / 4
#define TRAJ_PER_BLK 4096
#define F4_PER_BLK   6144         // TRAJ_PER_BLK * 6 / 4
#define NPROD 192                 // producer blocks, 8 items each -> 1536
#define PROD_PER_BATCH 6
#define CONS_PER_BATCH 64
#define GRID_BLKS 2048
#define SYNC_STRIDE 64            // ints -> 256 B between sync slots

// Device state (zero-initialized; per-batch reset at end of each launch)
__device__ float g_q0[B * L * R];
__device__ int   g_cnt[B * SYNC_STRIDE];   // producer-arrival counters
__device__ int   g_fin[B * SYNC_STRIDE];   // consumer-finish counters

// ---------------------------------------------------------------------------
// Fused kernel v3 — minimal-prefix producer/consumer.
//   All 2048 blocks expand one tile (b = bid>>6, xb = bid&63).
//   Blocks 0..191 first produce: block p computes items 8p..8p+7
//   (= all 8 digits of level l = p%6 for batch p/6), ONE barrier, then one
//   red.release.gpu.add on the batch counter.
//   Consumers: threads tid<48 acquire-poll the counter, load their g_q0
//   element, single barrier, then the proven expand body.
// ---------------------------------------------------------------------------
__global__ void __launch_bounds__(512) zdec_fused_kernel(
    const float* __restrict__ phi,   // (B, L)
    const float* __restrict__ rp,    // (L, R, 1)
    const float* __restrict__ W1,    // (H, 2)
    const float* __restrict__ b1,
    const float* __restrict__ W2,    // (H, H)
    const float* __restrict__ b2,
    const float* __restrict__ W3,    // (OUT, H) — row 0 only
    const float* __restrict__ b3,
    float* __restrict__ out)
{
    __shared__ union {
        struct {
            float w2[H * 65];
            float h1[8][H];
            float red[8][2];
        } p;
        float sq[L * R];
    } sm;

    const int bid = blockIdx.x;
    const int tid = threadIdx.x;

    // consumer tile mapping + address math hoisted before any waiting
    const int b  = bid >> 6;                 // batch (slow — proven locality)
    const int xb = bid & 63;                 // tile
    const int n_blk = xb * TRAJ_PER_BLK;
    float4* op = reinterpret_cast<float4*>(out)
               + (size_t)b * F4_PER_B + (size_t)xb * F4_PER_BLK;

    // ---------------- producer phase (blocks 0..191) ----------------------
    if (bid < NPROD) {
        const int item = tid >> 6;           // 0..7
        const int j    = tid & 63;           // hidden lane
        const int gi   = bid * 8 + item;     // item 0..1535
        const int pb   = bid / PROD_PER_BATCH;
        const int lr   = gi - pb * (L * R);
        const int l    = lr >> 3;

        // stage W2 via float4 (coalesced), 65-pitch conflict-free layout
#pragma unroll
        for (int t = tid; t < (H * H) / 4; t += 512) {
            const float4 w = reinterpret_cast<const float4*>(W2)[t];
            const int base = t * 4;
            float* d = &sm.p.w2[(base >> 6) * 65 + (base & 63)];
            d[0] = w.x; d[1] = w.y; d[2] = w.z; d[3] = w.w;
        }

        // h1 has no dependence on the staged W2 — write it immediately,
        // one barrier covers both.
        const float2 w1   = reinterpret_cast<const float2*>(W1)[j];
        const float  x    = rp[lr];
        const float  pphi = phi[pb * L + l];
        sm.p.h1[item][j]  = fmaxf(fmaf(w1.x, x, fmaf(w1.y, pphi, b1[j])), 0.0f);
        __syncthreads();

        float acc = b2[j];
#pragma unroll
        for (int k = 0; k < H; k++)
            acc = fmaf(sm.p.w2[j * 65 + k], sm.p.h1[item][k], acc);

        float q = W3[j] * fmaxf(acc, 0.0f);
#pragma unroll
        for (int off = 16; off > 0; off >>= 1)
            q += __shfl_xor_sync(0xffffffffu, q, off);
        if ((j & 31) == 0) sm.p.red[item][j >> 5] = q;
        __syncthreads();
        if (j == 0)
            g_q0[gi] = sm.p.red[item][0] + sm.p.red[item][1] + b3[0];

        // order g_q0 stores before the release-add
        __syncthreads();
        if (tid == 0)
            asm volatile("red.release.gpu.global.add.u32 [%0], %1;"
                         :: "l"(&g_cnt[pb * SYNC_STRIDE]), "r"(1) : "memory");
    }

    // ---------------- consumer phase (all blocks) --------------------------
    // tid<48: poll the batch counter, then load this thread's q0 element.
    if (tid < L * R) {
        int c;
        int spins = 0;
        do {
            asm volatile("ld.acquire.gpu.global.u32 %0, [%1];"
                         : "=r"(c) : "l"(&g_cnt[b * SYNC_STRIDE]) : "memory");
            if (c < PROD_PER_BATCH && ++spins > 48) __nanosleep(16);
        } while (c < PROD_PER_BATCH);
        sm.sq[tid] = g_q0[b * (L * R) + tid];
    }
    __syncthreads();

#pragma unroll
    for (int it = 0; it < F4_PER_BLK / 512; it++) {
        const int jl_blk = it * 512 + tid;
        const int ch  = jl_blk / 768;
        const int jl  = jl_blk - ch * 768;             // 0..767 within chunk
        const int nc  = n_blk + ch * 512;
        const float c3 = sm.sq[24 + ((nc >> 9)  & 7)];
        const float c4 = sm.sq[32 + ((nc >> 12) & 7)];
        const float c5 = sm.sq[40 + ((nc >> 15) & 7)];

        const int n   = (2 * jl) / 3;                  // local traj 0..511
        const int pat = jl % 3;
        const int d0 = n & 7;
        const int d1 = (n >> 3) & 7;
        const int d2 = (n >> 6) & 7;

        float4 v;
        if (pat == 0) {
            v.x = sm.sq[d0];  v.y = sm.sq[8 + d1];  v.z = sm.sq[16 + d2];  v.w = c3;
        } else if (pat == 1) {
            v.x = c4;  v.y = c5;  v.z = sm.sq[d0 + 1];  v.w = sm.sq[8 + d1];
        } else {
            v.x = sm.sq[16 + d2];  v.y = c3;  v.z = c4;  v.w = c5;
        }
        __stcs(op + jl_blk, v);
    }

    // ---------------- replay reset (per-batch, staggered) ------------------
    __syncthreads();
    if (tid == 0) {
        const int old = atomicAdd(&g_fin[b * SYNC_STRIDE], 1);
        if (old == CONS_PER_BATCH - 1) {
            g_cnt[b * SYNC_STRIDE] = 0;
            g_fin[b * SYNC_STRIDE] = 0;
            __threadfence();
        }
    }
}

// ---------------------------------------------------------------------------
extern "C" void kernel_launch(void* const* d_in, const int* in_sizes, int n_in,
                              void* d_out, int out_size)
{
    const float* phi = (const float*)d_in[0];
    const float* rp  = (const float*)d_in[1];
    const float* W1  = (const float*)d_in[2];
    const float* b1  = (const float*)d_in[3];
    const float* W2  = (const float*)d_in[4];
    const float* b2  = (const float*)d_in[5];
    const float* W3  = (const float*)d_in[6];
    const float* b3  = (const float*)d_in[7];
    float* out = (float*)d_out;

    zdec_fused_kernel<<<GRID_BLKS, 512>>>(phi, rp, W1, b1, W2, b2, W3, b3, out);
}